// round 15
// baseline (speedup 1.0000x reference)
#include <cuda_runtime.h>
#include <math.h>

// ISTFT: BC=64; F=513; T=1024; n_fft=1024; hop=256.
// R11/R14 core: radix-8 Stockham x3; C2R pack + stage 0 fused in registers
// (conjugate-pair threads over 8 frames); stages 1-2 + OLA as 2 passes of 4
// x 64-thread teams; smem twiddle table; 3 CTAs/SM.
// This round: (a) Hann from conflict-free pair table (kills 4 serial rotation
// chains/thread), (b) unified pack (bfly8+stores hoisted out of the pp==0
// branch -> warp-0 divergence cost ~3x smaller).

#define OUT_PER_BC 262400
#define NBLK 64               // t-group blocks per bc (16 frames each)
#define ACC_F2 2432           // 4864 floats
#define BUFS 578              // buf row stride (f2)

// dynamic smem layout (float2 units)
#define OFF_ACC (8 * BUFS)              // 4624
#define OFF_TW  (OFF_ACC + ACC_F2)      // 7056
#define OFF_HN  (OFF_TW + 513)          // 7569
#define SMEM_F2 (OFF_HN + 512)          // 8081 f2 = 64648 B

__device__ __forceinline__ float2 cmul(float2 a, float2 b) {
    return make_float2(a.x * b.x - a.y * b.y, a.x * b.y + a.y * b.x);
}
__device__ __forceinline__ float2 cadd(float2 a, float2 b) { return make_float2(a.x + b.x, a.y + b.y); }
__device__ __forceinline__ float2 csub(float2 a, float2 b) { return make_float2(a.x - b.x, a.y - b.y); }
__device__ __forceinline__ float2 cmuli(float2 a) { return make_float2(-a.y, a.x); }  // * i

__device__ __forceinline__ int P(int i) { return i + (i >> 3); }  // smem pad swizzle

__device__ __forceinline__ void teambar(int id) {      // 64-thread (2-warp) barrier
    asm volatile("bar.sync %0, %1;" :: "r"(id), "r"(64) : "memory");
}

// radix-8 inverse butterfly: b[u] = sum_t a[t] * e^{+2*pi*i*t*u/8}
__device__ __forceinline__ void bfly8(const float2* a, float2* b) {
    const float r = 0.70710678118654752f;
    float2 p0 = cadd(a[0], a[4]), p1 = csub(a[0], a[4]);
    float2 p2 = cadd(a[2], a[6]), p3 = cmuli(csub(a[2], a[6]));
    float2 e0 = cadd(p0, p2), e2 = csub(p0, p2), e1 = cadd(p1, p3), e3 = csub(p1, p3);
    float2 q0 = cadd(a[1], a[5]), q1 = csub(a[1], a[5]);
    float2 q2 = cadd(a[3], a[7]), q3 = cmuli(csub(a[3], a[7]));
    float2 o0 = cadd(q0, q2), o2 = csub(q0, q2), o1 = cadd(q1, q3), o3 = csub(q1, q3);
    b[0] = cadd(e0, o0); b[4] = csub(e0, o0);
    float2 w1 = make_float2(r, r), w3 = make_float2(-r, r);
    float2 t1 = cmul(o1, w1); b[1] = cadd(e1, t1); b[5] = csub(e1, t1);
    float2 t2 = cmuli(o2);    b[2] = cadd(e2, t2); b[6] = csub(e2, t2);
    float2 t3 = cmul(o3, w3); b[3] = cadd(e3, t3); b[7] = csub(e3, t3);
}

// zero the 63 overlap strips per bc: out[bc, 4096x-512 .. 4096x+256), x=1..63
__global__ void zero_strips_kernel(float* __restrict__ out) {
    int e = blockIdx.x * 256 + threadIdx.x;      // float4 index
    if (e >= 64 * 63 * 192) return;
    int i = e % 192;
    int r = e / 192;
    int x = r % 63 + 1;
    int bc = r / 63;
    float4* p = (float4*)(out + (size_t)bc * OUT_PER_BC + 4096 * x - 512);
    p[i] = make_float4(0.f, 0.f, 0.f, 0.f);
}

__global__ void __launch_bounds__(256, 3) istft_kernel(const float2* __restrict__ in,
                                                       float* __restrict__ out) {
    extern __shared__ float2 sm[];
    float2 (*buf)[BUFS] = (float2(*)[BUFS])sm;   // 8 frame rows
    float2* acc2  = sm + OFF_ACC;                // overlap-add accumulator
    float2* tw    = sm + OFF_TW;                 // e^{+2pi i k/1024}, k=0..512
    float2* hannp = sm + OFF_HN;                 // (hann(2m), hann(2m+1)), m=0..511

    const int tid = threadIdx.x;
    const int bc = blockIdx.y;
    const int xb = blockIdx.x;
    const int tbase = xb * 16;

    // ---- tables; zero only the add-only head of acc (f2 [0,384)) ----
    for (int i = tid; i < 513; i += 256) {
        float s, c;
        __sincosf(6.283185307179586f * (float)i / 1024.0f, &s, &c);
        tw[i] = make_float2(c, s);
    }
    for (int i = tid; i < 512; i += 256) {
        float c0 = __cosf(6.283185307179586f * (float)(2 * i) / 1024.0f);
        float c1 = __cosf(6.283185307179586f * (float)(2 * i + 1) / 1024.0f);
        hannp[i] = make_float2(0.5f - 0.5f * c0, 0.5f - 0.5f * c1);
    }
    for (int i = tid; i < 384; i += 256) acc2[i] = make_float2(0.f, 0.f);
    __syncthreads();

    const int jf = tid >> 6;        // team id (stages 1-2/OLA)
    const int lt = tid & 63;        // lane within team
    const int jj = lt >> 3, kk = lt & 7;
    const int jp = tid & 7;         // frame within super-group (pack/stage0)
    const int pp = tid >> 3;        // conjugate pair-lane 0..31
    const float SC = 0.015625f;     // 1/2 pack * 1/512 ifft * sqrt(1024) * 1/2 coeff

    for (int sg = 0; sg < 2; sg++) {
        // ==== fused C2R pack + stage 0 (8 frames, registers only). Unified:
        //      loads, bfly8s and stores are branch-free; only the C-combine
        //      differs for the self-conjugate lane pp==0. ====
        {
            const float2* base = in + (size_t)bc * 513 * 1024 + tbase + 8 * sg + jp;
            const int offA = pp;                               // set A bins: offA+64u
            const int offB = (pp == 0) ? 32 : (64 - pp);       // set B bins: offB+64u
            float2 Xa[8], Xb[8], Ca[8], Cb[8], B[8];
            #pragma unroll
            for (int u = 0; u < 8; u++) Xa[u] = base[(size_t)(offA + 64 * u) * 1024];
            #pragma unroll
            for (int u = 0; u < 8; u++) Xb[u] = base[(size_t)(offB + 64 * u) * 1024];
            if (pp == 0) {
                // set A = {64u} self-conjugate (+Nyquist); set B = {32+64u} self-conjugate
                float2 ny = base[(size_t)512 * 1024];
                Ca[0] = make_float2((Xa[0].x + ny.x) * SC, (Xa[0].x - ny.x) * SC);
                #pragma unroll
                for (int u = 1; u < 8; u++) {
                    float2 X = Xa[u], Y = Xa[8 - u];          // X[512-64u]
                    float2 A = make_float2(X.x + Y.x, X.y - Y.y);
                    float2 D = make_float2(X.x - Y.x, X.y + Y.y);
                    float2 wD = cmul(tw[64 * u], D);
                    Ca[u] = make_float2((A.x - wD.y) * SC, (A.y + wD.x) * SC);
                }
                #pragma unroll
                for (int u = 0; u < 8; u++) {
                    float2 X = Xb[u], Y = Xb[7 - u];          // X[512-(32+64u)]
                    float2 A = make_float2(X.x + Y.x, X.y - Y.y);
                    float2 D = make_float2(X.x - Y.x, X.y + Y.y);
                    float2 wD = cmul(tw[32 + 64 * u], D);
                    Cb[u] = make_float2((A.x - wD.y) * SC, (A.y + wD.x) * SC);
                }
            } else {
                // generic conjugate pair (pp, 64-pp): each bin read once
                #pragma unroll
                for (int u = 0; u < 8; u++) {
                    float2 X = Xa[u], Y = Xb[7 - u];          // X[512-k], k = pp+64u
                    float2 A = make_float2(X.x + Y.x, X.y - Y.y);
                    float2 D = make_float2(X.x - Y.x, X.y + Y.y);
                    float2 wD = cmul(tw[pp + 64 * u], D);
                    Ca[u]     = make_float2((A.x - wD.y) * SC, ( A.y + wD.x) * SC);
                    Cb[7 - u] = make_float2((A.x + wD.y) * SC, (-A.y + wD.x) * SC);
                }
            }
            bfly8(Ca, B);
            #pragma unroll
            for (int u = 0; u < 8; u++) buf[jp][P(offA + 64 * u)] = B[u];
            bfly8(Cb, B);
            #pragma unroll
            for (int u = 0; u < 8; u++) buf[jp][P(offB + 64 * u)] = B[u];
        }
        __syncthreads();

        // ==== stages 1-2 + window + OLA: 2 passes of 4 frames (order-preserving) ====
        for (int pass = 0; pass < 2; pass++) {
            const int fj = 4 * pass + jf;          // buf row; team-private this pass
            float2 a[8], b[8];

            // ---- stage 1: l=8, twiddles via log-depth power tree of tw[16*jj] ----
            #pragma unroll
            for (int t = 0; t < 8; t++) a[t] = buf[fj][P(kk + 64 * jj + 8 * t)];
            teambar(jf + 1);
            {
                float2 w1 = tw[16 * jj];
                float2 w2 = cmul(w1, w1);
                float2 w3 = cmul(w2, w1);
                float2 w4 = cmul(w2, w2);
                float2 w5 = cmul(w3, w2);
                float2 w6 = cmul(w3, w3);
                float2 w7 = cmul(w4, w3);
                a[1] = cmul(a[1], w1); a[2] = cmul(a[2], w2); a[3] = cmul(a[3], w3);
                a[4] = cmul(a[4], w4); a[5] = cmul(a[5], w5); a[6] = cmul(a[6], w6);
                a[7] = cmul(a[7], w7);
            }
            bfly8(a, b);
            #pragma unroll
            for (int u = 0; u < 8; u++) buf[fj][P(kk + 8 * jj + 64 * u)] = b[u];
            teambar(jf + 1);

            // ---- stage 2: l=64, twiddles via power tree of tw[2*lt] ----
            #pragma unroll
            for (int t = 0; t < 8; t++) a[t] = buf[fj][P(8 * lt + t)];
            {
                float2 w1 = tw[2 * lt];
                float2 w2 = cmul(w1, w1);
                float2 w3 = cmul(w2, w1);
                float2 w4 = cmul(w2, w2);
                float2 w5 = cmul(w3, w2);
                float2 w6 = cmul(w3, w3);
                float2 w7 = cmul(w4, w3);
                a[1] = cmul(a[1], w1); a[2] = cmul(a[2], w2); a[3] = cmul(a[3], w3);
                a[4] = cmul(a[4], w4); a[5] = cmul(a[5], w5); a[6] = cmul(a[6], w6);
                a[7] = cmul(a[7], w7);
            }
            bfly8(a, b);   // b[u] = z[lt + 64u]; even sample in .x, odd in .y

            // ---- Hann from pair table (conflict-free stride-1 LDS) ----
            #pragma unroll
            for (int u = 0; u < 8; u++) {
                float2 hh = hannp[lt + (u << 6)];
                b[u].x *= hh.x;
                b[u].y *= hh.y;
            }

            // ---- OLA: chunks 6,7 are this frame's first touch (position-disjoint
            //      across teams) -> store; then chunks 0..5 add in 3 CTA-synced
            //      rounds (per-round team regions disjoint). ----
            const int offh = ((sg << 3) + (pass << 2) + jf) << 7;   // 128*F in f2 units
            acc2[offh + lt + (6 << 6)] = b[6];
            acc2[offh + lt + (7 << 6)] = b[7];
            __syncthreads();
            #pragma unroll
            for (int c = 0; c < 3; c++) {
                #pragma unroll
                for (int h = 0; h < 2; h++) {
                    int u = 2 * c + h;
                    int m = lt + (u << 6);
                    float2 v = acc2[offh + m];
                    v.x += b[u].x; v.y += b[u].y;
                    acc2[offh + m] = v;
                }
                __syncthreads();
            }
        }
    }

    // ---- writeout (R10-proven) ----
    // head floats [0,768): xb==0 sole owner (store, crop 512); else atomicAdd strip.
    // body f2 [384,2048): sole owner -> float4 stores.
    // tail f2 [2048,2432): xb==63 sole owner (store); else atomicAdd strip xb+1.
    const float* accf = (const float*)acc2;
    float* obase = out + (size_t)bc * OUT_PER_BC;
    const int q0 = tbase << 8;   // 256 * tbase (floats)
    if (xb == 0) {
        for (int idx = tid; idx < 768; idx += 256)
            if (idx >= 512) obase[idx - 512] = accf[idx];
    } else {
        for (int idx = tid; idx < 768; idx += 256)
            atomicAdd(&obase[q0 + idx - 512], accf[idx]);
    }
    for (int k = tid; k < 832; k += 256) {          // body: 1664 f2 as 832 f4
        int idx2 = 384 + 2 * k;
        float4 v = ((const float4*)acc2)[idx2 >> 1];
        *(float4*)(obase + q0 + 2 * idx2 - 512) = v;
    }
    if (xb == NBLK - 1) {
        for (int idx2 = 2048 + tid; idx2 < ACC_F2; idx2 += 256) {
            int p = q0 + 2 * idx2 - 512;
            *(float2*)(obase + p) = acc2[idx2];
        }
    } else {
        for (int idx2 = 2048 + tid; idx2 < ACC_F2; idx2 += 256) {
            int p = q0 + 2 * idx2 - 512;
            float2 v = acc2[idx2];
            atomicAdd(&obase[p], v.x);
            atomicAdd(&obase[p + 1], v.y);
        }
    }
}

extern "C" void kernel_launch(void* const* d_in, const int* in_sizes, int n_in,
                              void* d_out, int out_size) {
    const float2* in = (const float2*)d_in[0];
    float* out = (float*)d_out;
    const int smem_bytes = SMEM_F2 * sizeof(float2);   // 64648
    cudaFuncSetAttribute(istft_kernel, cudaFuncAttributeMaxDynamicSharedMemorySize, smem_bytes);
    // 1) zero only the overlap strips (independent of main kernel)
    int total_f4 = 64 * 63 * 192;
    zero_strips_kernel<<<(total_f4 + 255) / 256, 256>>>(out);
    // 2) main ISTFT
    dim3 grid(NBLK, 64);   // (t-groups, bc)
    istft_kernel<<<grid, 256, smem_bytes>>>(in, out);
}

// round 17
// speedup vs baseline: 1.5459x; 1.5459x over previous
#include <cuda_runtime.h>
#include <math.h>

// ISTFT: BC=64; F=513; T=1024; n_fft=1024; hop=256.
// R11 core (best, 112.6us): radix-8 Stockham x3; C2R pack + stage 0 fused in
// registers (conjugate-pair threads over 8 frames); stages 1-2 + OLA as 2
// passes of 4 x 64-thread teams; smem twiddle table; 3 CTAs/SM.
// This round: cadd/csub as packed f32x2 (add.rn.f32x2 / fma.rn.f32x2) --
// halves the FADD instruction stream inside bfly8, identical .rn arithmetic.

#define OUT_PER_BC 262400
#define NBLK 64               // t-group blocks per bc (16 frames each)
#define ACC_F2 2432           // 4864 floats
#define BUFS 578              // buf row stride (f2)

// dynamic smem layout (float2 units)
#define OFF_ACC (8 * BUFS)              // 4624
#define OFF_TW  (OFF_ACC + ACC_F2)      // 7056
#define SMEM_F2 (OFF_TW + 513)          // 7569 f2 = 60552 B

__device__ __forceinline__ float2 cmul(float2 a, float2 b) {
    return make_float2(a.x * b.x - a.y * b.y, a.x * b.y + a.y * b.x);
}
// packed elementwise add/sub: one SASS instruction each (sm_100+ f32x2 pipe)
__device__ __forceinline__ float2 cadd(float2 a, float2 b) {
    unsigned long long la = *reinterpret_cast<unsigned long long*>(&a);
    unsigned long long lb = *reinterpret_cast<unsigned long long*>(&b);
    unsigned long long lr;
    asm("add.rn.f32x2 %0, %1, %2;" : "=l"(lr) : "l"(la), "l"(lb));
    return *reinterpret_cast<float2*>(&lr);
}
__device__ __forceinline__ float2 csub(float2 a, float2 b) {
    // a - b = fma(b, (-1,-1), a)  (sub.f32x2 availability uncertain; fma is proven)
    const unsigned long long NEG1 = 0xBF800000BF800000ULL;   // (-1.0f, -1.0f)
    unsigned long long la = *reinterpret_cast<unsigned long long*>(&a);
    unsigned long long lb = *reinterpret_cast<unsigned long long*>(&b);
    unsigned long long lr;
    asm("fma.rn.f32x2 %0, %1, %2, %3;" : "=l"(lr) : "l"(lb), "l"(NEG1), "l"(la));
    return *reinterpret_cast<float2*>(&lr);
}
__device__ __forceinline__ float2 cmuli(float2 a) { return make_float2(-a.y, a.x); }  // * i

__device__ __forceinline__ int P(int i) { return i + (i >> 3); }  // smem pad swizzle

// radix-8 inverse butterfly: b[u] = sum_t a[t] * e^{+2*pi*i*t*u/8}
__device__ __forceinline__ void bfly8(const float2* a, float2* b) {
    const float r = 0.70710678118654752f;
    float2 p0 = cadd(a[0], a[4]), p1 = csub(a[0], a[4]);
    float2 p2 = cadd(a[2], a[6]), p3 = cmuli(csub(a[2], a[6]));
    float2 e0 = cadd(p0, p2), e2 = csub(p0, p2), e1 = cadd(p1, p3), e3 = csub(p1, p3);
    float2 q0 = cadd(a[1], a[5]), q1 = csub(a[1], a[5]);
    float2 q2 = cadd(a[3], a[7]), q3 = cmuli(csub(a[3], a[7]));
    float2 o0 = cadd(q0, q2), o2 = csub(q0, q2), o1 = cadd(q1, q3), o3 = csub(q1, q3);
    b[0] = cadd(e0, o0); b[4] = csub(e0, o0);
    float2 w1 = make_float2(r, r), w3 = make_float2(-r, r);
    float2 t1 = cmul(o1, w1); b[1] = cadd(e1, t1); b[5] = csub(e1, t1);
    float2 t2 = cmuli(o2);    b[2] = cadd(e2, t2); b[6] = csub(e2, t2);
    float2 t3 = cmul(o3, w3); b[3] = cadd(e3, t3); b[7] = csub(e3, t3);
}

// zero the 63 overlap strips per bc: out[bc, 4096x-512 .. 4096x+256), x=1..63
__global__ void zero_strips_kernel(float* __restrict__ out) {
    int e = blockIdx.x * 256 + threadIdx.x;      // float4 index
    if (e >= 64 * 63 * 192) return;
    int i = e % 192;
    int r = e / 192;
    int x = r % 63 + 1;
    int bc = r / 63;
    float4* p = (float4*)(out + (size_t)bc * OUT_PER_BC + 4096 * x - 512);
    p[i] = make_float4(0.f, 0.f, 0.f, 0.f);
}

__global__ void __launch_bounds__(256, 3) istft_kernel(const float2* __restrict__ in,
                                                       float* __restrict__ out) {
    extern __shared__ float2 sm[];
    float2 (*buf)[BUFS] = (float2(*)[BUFS])sm;   // 8 frame rows
    float2* acc2 = sm + OFF_ACC;                 // overlap-add accumulator
    float2* tw   = sm + OFF_TW;                  // e^{+2pi i k/1024}, k=0..512

    const int tid = threadIdx.x;
    const int bc = blockIdx.y;
    const int xb = blockIdx.x;
    const int tbase = xb * 16;

    // ---- table init; zero only the add-only head of acc (f2 [0,384)) ----
    for (int i = tid; i < 513; i += 256) {
        float s, c;
        __sincosf(6.283185307179586f * (float)i / 1024.0f, &s, &c);
        tw[i] = make_float2(c, s);
    }
    for (int i = tid; i < 384; i += 256) acc2[i] = make_float2(0.f, 0.f);
    __syncthreads();

    const int jf = tid >> 6;        // team id (stages 1-2/OLA)
    const int lt = tid & 63;        // lane within team
    const int jj = lt >> 3, kk = lt & 7;
    const int jp = tid & 7;         // frame within super-group (pack/stage0)
    const int pp = tid >> 3;        // conjugate pair-lane 0..31
    const float SC = 0.015625f;     // 1/2 pack * 1/512 ifft * sqrt(1024) * 1/2 coeff

    for (int sg = 0; sg < 2; sg++) {
        // ==== fused C2R pack + stage 0 (8 frames, registers only) ====
        {
            const float2* base = in + (size_t)bc * 513 * 1024 + tbase + 8 * sg + jp;
            float2 Ca[8], Cb[8], B[8];
            if (pp == 0) {
                // lane 0 set {64u} (+Nyquist) and lane 32 set {32+64u}, both self-conjugate
                float2 Xa[8], Xc[8];
                #pragma unroll
                for (int u = 0; u < 8; u++) Xa[u] = base[(size_t)(64 * u) * 1024];
                #pragma unroll
                for (int u = 0; u < 8; u++) Xc[u] = base[(size_t)(32 + 64 * u) * 1024];
                float2 ny = base[(size_t)512 * 1024];
                Ca[0] = make_float2((Xa[0].x + ny.x) * SC, (Xa[0].x - ny.x) * SC);
                #pragma unroll
                for (int u = 1; u < 8; u++) {
                    float2 X = Xa[u], Y = Xa[8 - u];          // X[512-64u] = Xa[8-u]
                    float2 A = make_float2(X.x + Y.x, X.y - Y.y);
                    float2 D = make_float2(X.x - Y.x, X.y + Y.y);
                    float2 wD = cmul(tw[64 * u], D);
                    Ca[u] = make_float2((A.x - wD.y) * SC, (A.y + wD.x) * SC);
                }
                #pragma unroll
                for (int u = 0; u < 8; u++) {
                    float2 X = Xc[u], Y = Xc[7 - u];          // X[512-32-64u] = Xc[7-u]
                    float2 A = make_float2(X.x + Y.x, X.y - Y.y);
                    float2 D = make_float2(X.x - Y.x, X.y + Y.y);
                    float2 wD = cmul(tw[32 + 64 * u], D);
                    Cb[u] = make_float2((A.x - wD.y) * SC, (A.y + wD.x) * SC);
                }
                bfly8(Ca, B);
                #pragma unroll
                for (int u = 0; u < 8; u++) buf[jp][P(64 * u)] = B[u];
                bfly8(Cb, B);
                #pragma unroll
                for (int u = 0; u < 8; u++) buf[jp][P(32 + 64 * u)] = B[u];
            } else {
                // lanes (pp, 64-pp): bins {pp+64u} and {(64-pp)+64u}, each read once
                float2 Xa[8], Xb[8];
                #pragma unroll
                for (int u = 0; u < 8; u++) Xa[u] = base[(size_t)(pp + 64 * u) * 1024];
                #pragma unroll
                for (int u = 0; u < 8; u++) Xb[u] = base[(size_t)((64 - pp) + 64 * u) * 1024];
                #pragma unroll
                for (int u = 0; u < 8; u++) {
                    float2 X = Xa[u], Y = Xb[7 - u];          // X[512-k] for k = pp+64u
                    float2 A = make_float2(X.x + Y.x, X.y - Y.y);
                    float2 D = make_float2(X.x - Y.x, X.y + Y.y);
                    float2 wD = cmul(tw[pp + 64 * u], D);
                    Ca[u]     = make_float2((A.x - wD.y) * SC, ( A.y + wD.x) * SC);
                    Cb[7 - u] = make_float2((A.x + wD.y) * SC, (-A.y + wD.x) * SC);
                }
                bfly8(Ca, B);
                #pragma unroll
                for (int u = 0; u < 8; u++) buf[jp][P(pp + 64 * u)] = B[u];
                bfly8(Cb, B);
                #pragma unroll
                for (int u = 0; u < 8; u++) buf[jp][P((64 - pp) + 64 * u)] = B[u];
            }
        }
        __syncthreads();

        // ==== stages 1-2 + window + OLA: 2 passes of 4 frames (order-preserving) ====
        for (int pass = 0; pass < 2; pass++) {
            const int fj = 4 * pass + jf;          // buf row (0..7)
            float2 a[8], b[8];

            // ---- stage 1: l=8, twiddles by register rotation from tw[16*jj] ----
            #pragma unroll
            for (int t = 0; t < 8; t++) a[t] = buf[fj][P(kk + 64 * jj + 8 * t)];
            __syncthreads();
            {
                float2 w = tw[16 * jj];
                float2 cw = w;
                a[1] = cmul(a[1], cw);
                #pragma unroll
                for (int t = 2; t < 8; t++) { cw = cmul(cw, w); a[t] = cmul(a[t], cw); }
            }
            bfly8(a, b);
            #pragma unroll
            for (int u = 0; u < 8; u++) buf[fj][P(kk + 8 * jj + 64 * u)] = b[u];
            __syncthreads();

            // ---- stage 2: l=64, twiddles from tw[2*lt]; then window ----
            #pragma unroll
            for (int t = 0; t < 8; t++) a[t] = buf[fj][P(8 * lt + t)];
            {
                float2 w = tw[2 * lt];
                float2 cw = w;
                a[1] = cmul(a[1], cw);
                #pragma unroll
                for (int t = 2; t < 8; t++) { cw = cmul(cw, w); a[t] = cmul(a[t], cw); }
            }
            bfly8(a, b);   // b[u] = z[lt + 64u]; even sample in .x, odd in .y

            // Hann: h(s) = 0.5 - 0.5 cos(2 pi s/1024); rotate by e^{i pi/4} per u
            {
                const float R = 0.70710678118654752f;
                float2 e = tw[2 * lt];
                float2 o = tw[2 * lt + 1];
                #pragma unroll
                for (int u = 0; u < 8; u++) {
                    b[u].x *= (0.5f - 0.5f * e.x);
                    b[u].y *= (0.5f - 0.5f * o.x);
                    float ex = (e.x - e.y) * R, ey = (e.x + e.y) * R; e = make_float2(ex, ey);
                    float ox = (o.x - o.y) * R, oy = (o.x + o.y) * R; o = make_float2(ox, oy);
                }
            }

            // ---- OLA: chunks 6,7 are this frame's first touch -> store; then
            //      chunks 0..5 add in 3 synced rounds (regions distinct per round). ----
            const int offh = ((sg << 3) + (pass << 2) + jf) << 7;   // 128*F in f2 units
            acc2[offh + lt + (6 << 6)] = b[6];
            acc2[offh + lt + (7 << 6)] = b[7];
            __syncthreads();
            #pragma unroll
            for (int c = 0; c < 3; c++) {
                #pragma unroll
                for (int h = 0; h < 2; h++) {
                    int u = 2 * c + h;
                    int m = lt + (u << 6);
                    float2 v = acc2[offh + m];
                    v.x += b[u].x; v.y += b[u].y;
                    acc2[offh + m] = v;
                }
                __syncthreads();
            }
        }
    }

    // ---- writeout (R10-proven) ----
    // head floats [0,768): xb==0 sole owner (store, crop 512); else atomicAdd strip.
    // body f2 [384,2048): sole owner -> float4 stores.
    // tail f2 [2048,2432): xb==63 sole owner (store); else atomicAdd strip xb+1.
    const float* accf = (const float*)acc2;
    float* obase = out + (size_t)bc * OUT_PER_BC;
    const int q0 = tbase << 8;   // 256 * tbase (floats)
    if (xb == 0) {
        for (int idx = tid; idx < 768; idx += 256)
            if (idx >= 512) obase[idx - 512] = accf[idx];
    } else {
        for (int idx = tid; idx < 768; idx += 256)
            atomicAdd(&obase[q0 + idx - 512], accf[idx]);
    }
    for (int k = tid; k < 832; k += 256) {          // body: 1664 f2 as 832 f4
        int idx2 = 384 + 2 * k;
        float4 v = ((const float4*)acc2)[idx2 >> 1];
        *(float4*)(obase + q0 + 2 * idx2 - 512) = v;
    }
    if (xb == NBLK - 1) {
        for (int idx2 = 2048 + tid; idx2 < ACC_F2; idx2 += 256) {
            int p = q0 + 2 * idx2 - 512;
            *(float2*)(obase + p) = acc2[idx2];
        }
    } else {
        for (int idx2 = 2048 + tid; idx2 < ACC_F2; idx2 += 256) {
            int p = q0 + 2 * idx2 - 512;
            float2 v = acc2[idx2];
            atomicAdd(&obase[p], v.x);
            atomicAdd(&obase[p + 1], v.y);
        }
    }
}

extern "C" void kernel_launch(void* const* d_in, const int* in_sizes, int n_in,
                              void* d_out, int out_size) {
    const float2* in = (const float2*)d_in[0];
    float* out = (float*)d_out;
    const int smem_bytes = SMEM_F2 * sizeof(float2);   // 60552
    cudaFuncSetAttribute(istft_kernel, cudaFuncAttributeMaxDynamicSharedMemorySize, smem_bytes);
    // 1) zero only the overlap strips (independent of main kernel)
    int total_f4 = 64 * 63 * 192;
    zero_strips_kernel<<<(total_f4 + 255) / 256, 256>>>(out);
    // 2) main ISTFT
    dim3 grid(NBLK, 64);   // (t-groups, bc)
    istft_kernel<<<grid, 256, smem_bytes>>>(in, out);
}